// round 7
// baseline (speedup 1.0000x reference)
#include <cuda_runtime.h>
#include <cstdint>

#define BSZ 4
#define CS  1024
#define PS  1024
#define DIN 1024
#define H   16
#define D   64
#define T   2048
#define HD  (H * D)
#define SCALEF 0.125f

// ---------------- scratch (static device globals; allocation-free) ----------
__device__ float g_kv [(size_t)BSZ * T * 2 * HD];   // [b*T+t][2048]  k: 0..1023, v: 1024..2047
__device__ float g_q  [(size_t)BSZ * CS * HD];
__device__ float g_p  [(size_t)T * HD];
__device__ float g_pa [(size_t)H * BSZ * CS * T];   // [h][M][j]
__device__ float g_awv[(size_t)BSZ * CS * HD];      // tf32-rounded attention output

// tf32-rounded copies of GEMM sources
__device__ float r_input[(size_t)BSZ * CS * DIN];
__device__ float r_mem  [(size_t)BSZ * PS * DIN];
__device__ float r_pos  [(size_t)T * DIN];
__device__ float r_wkv  [(size_t)DIN * 2 * HD];
__device__ float r_wq   [(size_t)DIN * HD];
__device__ float r_wp   [(size_t)DIN * HD];
__device__ float r_wout [(size_t)HD * DIN];

// ---------------- tf32 helpers ----------------------------------------------
__device__ __forceinline__ uint32_t f2tf(float x) {
    uint32_t u;
    asm("cvt.rna.tf32.f32 %0, %1;" : "=r"(u) : "f"(x));
    return u;
}

#define MMA_TF32(c, a, b) \
    asm volatile("mma.sync.aligned.m16n8k8.row.col.f32.tf32.tf32.f32 " \
                 "{%0,%1,%2,%3},{%4,%5,%6,%7},{%8,%9},{%0,%1,%2,%3};" \
                 : "+f"(c[0]), "+f"(c[1]), "+f"(c[2]), "+f"(c[3]) \
                 : "r"(a[0]), "r"(a[1]), "r"(a[2]), "r"(a[3]), "r"(b[0]), "r"(b[1]))

__device__ __forceinline__ void cp16(uint32_t* smem_dst, const float* gmem_src) {
    uint32_t sa = (uint32_t)__cvta_generic_to_shared(smem_dst);
    asm volatile("cp.async.cg.shared.global [%0], [%1], 16;" :: "r"(sa), "l"(gmem_src));
}
#define CP_COMMIT asm volatile("cp.async.commit_group;")
#define CP_WAIT1  asm volatile("cp.async.wait_group 1;")
#define CP_WAIT0  asm volatile("cp.async.wait_group 0;")

// ---------------- elementwise tf32 rounding pass ------------------------------
__global__ void round_tf32(const float* __restrict__ src, float* __restrict__ dst, int n4)
{
    int i = blockIdx.x * blockDim.x + threadIdx.x;
    if (i < n4) {
        float4 v = *(const float4*)(src + (size_t)i * 4);
        uint4 r;
        r.x = f2tf(v.x); r.y = f2tf(v.y); r.z = f2tf(v.z); r.w = f2tf(v.w);
        *(uint4*)(dst + (size_t)i * 4) = r;
    }
}

// ---------------- 64x64-warp-tile GEMM pieces ---------------------------------
// block tile 128(M) x 256(N), 8 warps = 2(m) x 4(n), warp 64x64, K-chunk 32
#define AS_LD 36     // A: 128 x 32, bank (4m+k)%32 conflict-free
#define BS_LD 264    // B: 32 x 256, bank (8k+n)%32 conflict-free
#define STG_W (128 * AS_LD + 32 * BS_LD)   // 13056 words / stage
#define MM_SMEM (3 * STG_W * 4)            // 156672 B

// one K=32 chunk of compute; acc[mt][nt][4]
__device__ __forceinline__ void mma_chunk64(float acc[4][8][4],
                                            const uint32_t* __restrict__ As,
                                            const uint32_t* __restrict__ Bs,
                                            int wm, int wn, int lane)
{
    int g = lane >> 2, t = lane & 3;
#pragma unroll
    for (int ks = 0; ks < 4; ks++) {
        uint32_t a[4][4];
#pragma unroll
        for (int mt = 0; mt < 4; mt++) {
            int row = wm * 64 + mt * 16 + g;
            int col = ks * 8 + t;
            a[mt][0] = As[row * AS_LD + col];
            a[mt][1] = As[(row + 8) * AS_LD + col];
            a[mt][2] = As[row * AS_LD + col + 4];
            a[mt][3] = As[(row + 8) * AS_LD + col + 4];
        }
        uint32_t b[8][2];
#pragma unroll
        for (int nt = 0; nt < 8; nt++) {
            int brow = ks * 8 + t;
            int bcol = wn * 64 + nt * 8 + g;
            b[nt][0] = Bs[brow * BS_LD + bcol];
            b[nt][1] = Bs[(brow + 4) * BS_LD + bcol];
        }
#pragma unroll
        for (int mt = 0; mt < 4; mt++)
#pragma unroll
            for (int nt = 0; nt < 8; nt++)
                MMA_TF32(acc[mt][nt], a[mt], b[nt]);
    }
}

__device__ __forceinline__ void store_C64(float acc[4][8][4], float* C, int ldc,
                                          int m0, int n0, int wm, int wn, int lane)
{
    int g = lane >> 2, t = lane & 3;
#pragma unroll
    for (int mt = 0; mt < 4; mt++) {
#pragma unroll
        for (int nt = 0; nt < 8; nt++) {
            int row = m0 + wm * 64 + mt * 16 + g;
            int col = n0 + wn * 64 + nt * 8 + 2 * t;
            *(float2*)(C + (size_t)row * ldc + col) =
                make_float2(acc[mt][nt][0], acc[mt][nt][1]);
            *(float2*)(C + (size_t)(row + 8) * ldc + col) =
                make_float2(acc[mt][nt][2], acc[mt][nt][3]);
        }
    }
}

// stage A 128x32 (plain rows) + B 32x256 via cp.async
__device__ __forceinline__ void stage_A3(uint32_t* As, const float* __restrict__ A,
                                         int lda, int m0, int k0, int tid)
{
#pragma unroll
    for (int i = 0; i < 4; i++) {
        int s = tid + i * 256;
        int row = s >> 3, kq = (s & 7) * 4;
        cp16(&As[row * AS_LD + kq], A + (size_t)(m0 + row) * lda + k0 + kq);
    }
}
__device__ __forceinline__ void stage_B3(uint32_t* Bs, const float* __restrict__ B,
                                         int ldb, int n0, int k0, int tid)
{
#pragma unroll
    for (int i = 0; i < 8; i++) {
        int s = tid + i * 256;
        int k = s >> 6, n4 = (s & 63) * 4;
        cp16(&Bs[k * BS_LD + n4], B + (size_t)(k0 + k) * ldb + n0 + n4);
    }
}
// A rows gathered from [memory; input]
__device__ __forceinline__ void stage_A3_kv(uint32_t* As, int m0, int k0, int tid)
{
#pragma unroll
    for (int i = 0; i < 4; i++) {
        int s = tid + i * 256;
        int row = s >> 3, kq = (s & 7) * 4;
        int grow = m0 + row;
        int b = grow >> 11, tl = grow & (T - 1);
        const float* Arow = (tl < PS) ? (r_mem + (size_t)(b * PS + tl) * DIN)
                                      : (r_input + (size_t)(b * CS + tl - PS) * DIN);
        cp16(&As[row * AS_LD + kq], Arow + k0 + kq);
    }
}

// ---------------- pipelined GEMM (3-stage ring, 1 barrier/chunk) --------------
template <int KV>
__global__ __launch_bounds__(256, 1)
void mm_ca3(const float* __restrict__ A, const float* __restrict__ B,
            float* __restrict__ C, int M, int N, int K)
{
    extern __shared__ uint32_t dsm[];
    int tid = threadIdx.x, lane = tid & 31, w = tid >> 5;
    int wm = w >> 2, wn = w & 3;
    int m0 = blockIdx.y * 128, n0 = blockIdx.x * 256;

    float acc[4][8][4];
#pragma unroll
    for (int i = 0; i < 4; i++)
#pragma unroll
        for (int j = 0; j < 8; j++)
#pragma unroll
            for (int r = 0; r < 4; r++) acc[i][j][r] = 0.f;

    uint32_t* SA[3] = { dsm, dsm + STG_W, dsm + 2 * STG_W };
    uint32_t* SB[3] = { dsm + 128 * AS_LD, dsm + STG_W + 128 * AS_LD,
                        dsm + 2 * STG_W + 128 * AS_LD };

    int NC = K >> 5;
    // prologue: stage chunks 0,1
#pragma unroll
    for (int c = 0; c < 2; c++) {
        if (KV) stage_A3_kv(SA[c], m0, c * 32, tid);
        else    stage_A3(SA[c], A, K, m0, c * 32, tid);
        stage_B3(SB[c], B, N, n0, c * 32, tid);
        CP_COMMIT;
    }
    for (int k = 0; k < NC; k++) {
        if (k == NC - 1) { CP_WAIT0; } else { CP_WAIT1; }
        __syncthreads();            // chunk k visible; all warps done with k-1
        if (k + 2 < NC) {           // slot (k+2)%3 held chunk k-1 -> safe to refill
            int slot = (k + 2) % 3;
            if (KV) stage_A3_kv(SA[slot], m0, (k + 2) * 32, tid);
            else    stage_A3(SA[slot], A, K, m0, (k + 2) * 32, tid);
            stage_B3(SB[slot], B, N, n0, (k + 2) * 32, tid);
            CP_COMMIT;
        }
        mma_chunk64(acc, SA[k % 3], SB[k % 3], wm, wn, lane);
    }
    __syncthreads();
    store_C64(acc, C, N, m0, n0, wm, wn, lane);
}

// ---------------- position-attn GEMM (per head, K=64, NT, single-shot) --------
// g_pa[h][M][j] = sum_d (g_q[M,h*64+d]+v[h,d]) * g_p[j,h*64+d]
#define PA_ALD 68
#define PA_SMEM ((128 * PA_ALD + 256 * PA_ALD) * 4)   // 104448 B

__global__ __launch_bounds__(256, 1)
void mm_pa64(const float* __restrict__ vvec)
{
    extern __shared__ uint32_t psm[];
    uint32_t* As = psm;                       // 128 x 68 (q+v, K-major)
    uint32_t* Pns = psm + 128 * PA_ALD;       // 256 x 68 (p rows, K-major)

    int tid = threadIdx.x, lane = tid & 31, w = tid >> 5;
    int wm = w >> 2, wn = w & 3;
    int h = blockIdx.z;
    int m0 = blockIdx.y * 128, n0 = blockIdx.x * 256;
    int g = lane >> 2, t = lane & 3;

    // stage A = q + v (tf32), 128 x 64
#pragma unroll
    for (int i = 0; i < 8; i++) {
        int s = tid + i * 256;
        int r = s >> 4, kq = (s & 15) * 4;
        float4 a = *(const float4*)(g_q + (size_t)(m0 + r) * HD + h * D + kq);
        float4 vx = *(const float4*)(vvec + h * D + kq);
        uint4 u;
        u.x = f2tf(a.x + vx.x); u.y = f2tf(a.y + vx.y);
        u.z = f2tf(a.z + vx.z); u.w = f2tf(a.w + vx.w);
        *(uint4*)&As[r * PA_ALD + kq] = u;
    }
    // stage B = p rows (tf32), 256 x 64
#pragma unroll
    for (int i = 0; i < 16; i++) {
        int s = tid + i * 256;
        int r = s >> 4, kq = (s & 15) * 4;
        float4 p4 = *(const float4*)(g_p + (size_t)(n0 + r) * HD + h * D + kq);
        uint4 u;
        u.x = f2tf(p4.x); u.y = f2tf(p4.y); u.z = f2tf(p4.z); u.w = f2tf(p4.w);
        *(uint4*)&Pns[r * PA_ALD + kq] = u;
    }
    __syncthreads();

    float acc[4][8][4];
#pragma unroll
    for (int i = 0; i < 4; i++)
#pragma unroll
        for (int j = 0; j < 8; j++)
#pragma unroll
            for (int r = 0; r < 4; r++) acc[i][j][r] = 0.f;

#pragma unroll
    for (int ks = 0; ks < 8; ks++) {
        uint32_t a[4][4];
#pragma unroll
        for (int mt = 0; mt < 4; mt++) {
            int row = wm * 64 + mt * 16 + g;
            int col = ks * 8 + t;
            a[mt][0] = As[row * PA_ALD + col];
            a[mt][1] = As[(row + 8) * PA_ALD + col];
            a[mt][2] = As[row * PA_ALD + col + 4];
            a[mt][3] = As[(row + 8) * PA_ALD + col + 4];
        }
        uint32_t b[8][2];
#pragma unroll
        for (int nt = 0; nt < 8; nt++) {
            int bcol = wn * 64 + nt * 8 + g;
            b[nt][0] = Pns[bcol * PA_ALD + ks * 8 + t];
            b[nt][1] = Pns[bcol * PA_ALD + ks * 8 + t + 4];
        }
#pragma unroll
        for (int mt = 0; mt < 4; mt++)
#pragma unroll
            for (int nt = 0; nt < 8; nt++)
                MMA_TF32(acc[mt][nt], a[mt], b[nt]);
    }
    store_C64(acc, g_pa + (size_t)h * (BSZ * CS) * T, T, m0, n0, wm, wn, lane);
}

// ---------------- tensor-core flash attention with rel-shift gather -----------
#define AT_LD 68

__device__ __forceinline__ float pos_val(int h, int Mrow, int j) {
    int sp = j + BSZ * CS - Mrow;
    int add = (sp >= (T + 1)) + (sp >= 2 * (T + 1));
    int Mp = Mrow + add;
    int jp = sp - add * (T + 1);
    return (jp == 0) ? 0.f : __ldg(&g_pa[((size_t)h * (BSZ * CS) + Mp) * T + (jp - 1)]);
}

__global__ __launch_bounds__(256, 2)
void attn_tc(const float* __restrict__ u)
{
    extern __shared__ uint32_t sm[];
    uint32_t* Ks = sm;
    uint32_t* Vs = sm + 64 * AT_LD;
    uint32_t* Ps = sm + 128 * AT_LD;

    int tid = threadIdx.x, lane = tid & 31, w = tid >> 5;
    int b = blockIdx.z, h = blockIdx.y;
    int q0 = (int)(gridDim.x - 1 - blockIdx.x) * 128;
    int g = lane >> 2, t = lane & 3;

    for (int i = tid; i < 128 * 16; i += 256) {
        int r = i >> 4, d4 = (i & 15) * 4;
        float4 qv = *(const float4*)(g_q + (size_t)(b * CS + q0 + r) * HD + h * D + d4);
        float4 uv = *(const float4*)(u + h * D + d4);
        Ps[r * AT_LD + d4 + 0] = f2tf(qv.x + uv.x);
        Ps[r * AT_LD + d4 + 1] = f2tf(qv.y + uv.y);
        Ps[r * AT_LD + d4 + 2] = f2tf(qv.z + uv.z);
        Ps[r * AT_LD + d4 + 3] = f2tf(qv.w + uv.w);
    }
    __syncthreads();

    uint32_t qf[8][4];
    {
        int r0 = w * 16 + g;
#pragma unroll
        for (int ks = 0; ks < 8; ks++) {
            qf[ks][0] = Ps[r0 * AT_LD + ks * 8 + t];
            qf[ks][1] = Ps[(r0 + 8) * AT_LD + ks * 8 + t];
            qf[ks][2] = Ps[r0 * AT_LD + ks * 8 + t + 4];
            qf[ks][3] = Ps[(r0 + 8) * AT_LD + ks * 8 + t + 4];
        }
    }

    float of[8][4];
#pragma unroll
    for (int nt = 0; nt < 8; nt++)
#pragma unroll
        for (int r = 0; r < 4; r++) of[nt][r] = 0.f;
    float m0r = -1e30f, m1r = -1e30f, l0 = 0.f, l1 = 0.f;

    int iq_g = q0 + w * 16 + g;
    int Mrow_g = b * CS + iq_g, Mrow_g8 = Mrow_g + 8;
    int pr0 = (w * 16 + g) * AT_LD, pr8 = (w * 16 + g + 8) * AT_LD;
    int ntiles = q0 / 64 + 18;

    for (int tt = 0; tt < ntiles; tt++) {
        int j0 = tt * 64;
        __syncthreads();
        for (int i = tid; i < 64 * 16; i += 256) {
            int r = i >> 4, d4 = (i & 15) * 4;
            const float* kvrow = g_kv + (size_t)(b * T + j0 + r) * (2 * HD) + h * D;
            float4 k4 = *(const float4*)(kvrow + d4);
            float4 v4 = *(const float4*)(kvrow + HD + d4);
            Ks[r * AT_LD + d4 + 0] = f2tf(k4.x); Ks[r * AT_LD + d4 + 1] = f2tf(k4.y);
            Ks[r * AT_LD + d4 + 2] = f2tf(k4.z); Ks[r * AT_LD + d4 + 3] = f2tf(k4.w);
            Vs[r * AT_LD + d4 + 0] = f2tf(v4.x); Vs[r * AT_LD + d4 + 1] = f2tf(v4.y);
            Vs[r * AT_LD + d4 + 2] = f2tf(v4.z); Vs[r * AT_LD + d4 + 3] = f2tf(v4.w);
        }
        __syncthreads();

        float sf[8][4];
#pragma unroll
        for (int nt = 0; nt < 8; nt++) {
            sf[nt][0] = sf[nt][1] = sf[nt][2] = sf[nt][3] = 0.f;
#pragma unroll
            for (int ks = 0; ks < 8; ks++) {
                uint32_t bb[2];
                bb[0] = Ks[(nt * 8 + g) * AT_LD + ks * 8 + t];
                bb[1] = Ks[(nt * 8 + g) * AT_LD + ks * 8 + t + 4];
                MMA_TF32(sf[nt], qf[ks], bb);
            }
        }

        bool need_mask = (tt >= ntiles - 2);
#pragma unroll
        for (int nt = 0; nt < 8; nt++) {
            int j = j0 + nt * 8 + 2 * t;
            sf[nt][0] = (sf[nt][0] + pos_val(h, Mrow_g,  j))     * SCALEF;
            sf[nt][1] = (sf[nt][1] + pos_val(h, Mrow_g,  j + 1)) * SCALEF;
            sf[nt][2] = (sf[nt][2] + pos_val(h, Mrow_g8, j))     * SCALEF;
            sf[nt][3] = (sf[nt][3] + pos_val(h, Mrow_g8, j + 1)) * SCALEF;
            if (need_mask) {
                int lim0 = iq_g + PS, lim1 = lim0 + 8;
                if (j     > lim0) sf[nt][0] = -1e30f;
                if (j + 1 > lim0) sf[nt][1] = -1e30f;
                if (j     > lim1) sf[nt][2] = -1e30f;
                if (j + 1 > lim1) sf[nt][3] = -1e30f;
            }
        }

        float tm0 = -1e30f, tm1 = -1e30f;
#pragma unroll
        for (int nt = 0; nt < 8; nt++) {
            tm0 = fmaxf(tm0, fmaxf(sf[nt][0], sf[nt][1]));
            tm1 = fmaxf(tm1, fmaxf(sf[nt][2], sf[nt][3]));
        }
        tm0 = fmaxf(tm0, __shfl_xor_sync(0xffffffffu, tm0, 1));
        tm0 = fmaxf(tm0, __shfl_xor_sync(0xffffffffu, tm0, 2));
        tm1 = fmaxf(tm1, __shfl_xor_sync(0xffffffffu, tm1, 1));
        tm1 = fmaxf(tm1, __shfl_xor_sync(0xffffffffu, tm1, 2));
        float nm0 = fmaxf(m0r, tm0), nm1 = fmaxf(m1r, tm1);
        float cr0 = __expf(m0r - nm0), cr1 = __expf(m1r - nm1);

        float ps0 = 0.f, ps1 = 0.f;
#pragma unroll
        for (int nt = 0; nt < 8; nt++) {
            float e0 = __expf(sf[nt][0] - nm0);
            float e1 = __expf(sf[nt][1] - nm0);
            float e2 = __expf(sf[nt][2] - nm1);
            float e3 = __expf(sf[nt][3] - nm1);
            int col = nt * 8 + 2 * t;
            Ps[pr0 + col]     = f2tf(e0);
            Ps[pr0 + col + 1] = f2tf(e1);
            Ps[pr8 + col]     = f2tf(e2);
            Ps[pr8 + col + 1] = f2tf(e3);
            ps0 += e0 + e1;
            ps1 += e2 + e3;
        }
        ps0 += __shfl_xor_sync(0xffffffffu, ps0, 1);
        ps0 += __shfl_xor_sync(0xffffffffu, ps0, 2);
        ps1 += __shfl_xor_sync(0xffffffffu, ps1, 1);
        ps1 += __shfl_xor_sync(0xffffffffu, ps1, 2);
        l0 = l0 * cr0 + ps0;
        l1 = l1 * cr1 + ps1;
        m0r = nm0; m1r = nm1;
#pragma unroll
        for (int nt = 0; nt < 8; nt++) {
            of[nt][0] *= cr0; of[nt][1] *= cr0;
            of[nt][2] *= cr1; of[nt][3] *= cr1;
        }
        __syncwarp();

        uint32_t af[8][4];
#pragma unroll
        for (int ks = 0; ks < 8; ks++) {
            af[ks][0] = Ps[pr0 + ks * 8 + t];
            af[ks][1] = Ps[pr8 + ks * 8 + t];
            af[ks][2] = Ps[pr0 + ks * 8 + t + 4];
            af[ks][3] = Ps[pr8 + ks * 8 + t + 4];
        }
#pragma unroll
        for (int nt = 0; nt < 8; nt++) {
#pragma unroll
            for (int ks = 0; ks < 8; ks++) {
                uint32_t bb[2];
                bb[0] = Vs[(ks * 8 + t) * AT_LD + nt * 8 + g];
                bb[1] = Vs[(ks * 8 + t + 4) * AT_LD + nt * 8 + g];
                MMA_TF32(of[nt], af[ks], bb);
            }
        }
        __syncwarp();
    }

    float i0 = 1.f / l0, i1 = 1.f / l1;
    int orow = b * CS + q0 + w * 16 + g;
#pragma unroll
    for (int nt = 0; nt < 8; nt++) {
        int col = h * D + nt * 8 + 2 * t;
        float2 v0 = make_float2(__uint_as_float(f2tf(of[nt][0] * i0)),
                                __uint_as_float(f2tf(of[nt][1] * i0)));
        float2 v1 = make_float2(__uint_as_float(f2tf(of[nt][2] * i1)),
                                __uint_as_float(f2tf(of[nt][3] * i1)));
        *(float2*)(g_awv + (size_t)orow * HD + col) = v0;
        *(float2*)(g_awv + (size_t)(orow + 8) * HD + col) = v1;
    }
}

// ---------------- launch -------------------------------------------------------
extern "C" void kernel_launch(void* const* d_in, const int* in_sizes, int n_in,
                              void* d_out, int out_size)
{
    const float* input  = (const float*)d_in[0];
    const float* pos    = (const float*)d_in[1];
    const float* memory = (const float*)d_in[2];
    const float* u      = (const float*)d_in[3];
    const float* v      = (const float*)d_in[4];
    const float* Wkv    = (const float*)d_in[5];
    const float* Wq     = (const float*)d_in[6];
    const float* Wp     = (const float*)d_in[7];
    const float* Wout   = (const float*)d_in[8];
    float* out = (float*)d_out;

    float *pq, *pp, *pkv, *pawv;
    float *pri, *prm, *prp, *prkv, *prq, *prwp, *prwo;
    cudaGetSymbolAddress((void**)&pq,   g_q);
    cudaGetSymbolAddress((void**)&pp,   g_p);
    cudaGetSymbolAddress((void**)&pkv,  g_kv);
    cudaGetSymbolAddress((void**)&pawv, g_awv);
    cudaGetSymbolAddress((void**)&pri,  r_input);
    cudaGetSymbolAddress((void**)&prm,  r_mem);
    cudaGetSymbolAddress((void**)&prp,  r_pos);
    cudaGetSymbolAddress((void**)&prkv, r_wkv);
    cudaGetSymbolAddress((void**)&prq,  r_wq);
    cudaGetSymbolAddress((void**)&prwp, r_wp);
    cudaGetSymbolAddress((void**)&prwo, r_wout);

    const int ATT_SMEM = 256 * AT_LD * 4;   // 69632 B
    cudaFuncSetAttribute(mm_ca3<0>, cudaFuncAttributeMaxDynamicSharedMemorySize, MM_SMEM);
    cudaFuncSetAttribute(mm_ca3<1>, cudaFuncAttributeMaxDynamicSharedMemorySize, MM_SMEM);
    cudaFuncSetAttribute(mm_pa64,   cudaFuncAttributeMaxDynamicSharedMemorySize, PA_SMEM);
    cudaFuncSetAttribute(attn_tc,   cudaFuncAttributeMaxDynamicSharedMemorySize, ATT_SMEM);

    // pre-round GEMM sources to tf32-clean fp32
    auto rr = [](const float* s, float* d, int n) {
        round_tf32<<<(n / 4 + 255) / 256, 256>>>(s, d, n / 4);
    };
    rr(input,  pri,  BSZ * CS * DIN);
    rr(memory, prm,  BSZ * PS * DIN);
    rr(pos,    prp,  T * DIN);
    rr(Wkv,    prkv, DIN * 2 * HD);
    rr(Wq,     prq,  DIN * HD);
    rr(Wp,     prwp, DIN * HD);
    rr(Wout,   prwo, HD * DIN);

    // kv = [memory; input] @ W_kv       (8192 x 2048 x 1024)
    mm_ca3<1><<<dim3(8, 64), 256, MM_SMEM>>>(nullptr, prkv, pkv, BSZ * T, 2 * HD, DIN);
    // q = input @ W_q                   (4096 x 1024 x 1024)
    mm_ca3<0><<<dim3(4, 32), 256, MM_SMEM>>>(pri, prq, pq, BSZ * CS, HD, DIN);
    // p = pos_embs @ W_p                (2048 x 1024 x 1024)
    mm_ca3<0><<<dim3(4, 16), 256, MM_SMEM>>>(prp, prwp, pp, T, HD, DIN);
    // pos_attn per head                 (16 x 4096 x 2048 x 64)
    mm_pa64<<<dim3(8, 32, H), 256, PA_SMEM>>>(v);
    // tensor-core flash attention with rel-shift gather
    attn_tc<<<dim3(8, H, BSZ), 256, ATT_SMEM>>>(u);
    // out = awv @ W_out                 (4096 x 1024 x 1024)
    mm_ca3<0><<<dim3(4, 32), 256, MM_SMEM>>>(pawv, prwo, out, BSZ * CS, DIN, HD);
}

// round 13
// speedup vs baseline: 1.0933x; 1.0933x over previous
#include <cuda_runtime.h>
#include <cstdint>

#define BSZ 4
#define CS  1024
#define PS  1024
#define DIN 1024
#define H   16
#define D   64
#define T   2048
#define HD  (H * D)
#define SCALEF 0.125f

// ---------------- scratch (static device globals; allocation-free) ----------
__device__ float g_kv [(size_t)BSZ * T * 2 * HD];   // [b*T+t][2048] k:0..1023 v:1024..2047 (tf32-rounded)
__device__ float g_q  [(size_t)BSZ * CS * HD];
__device__ float g_p  [(size_t)T * HD];
__device__ float g_pa [(size_t)H * BSZ * CS * T];   // [h][M][j] SHIFTED+SCALED position scores
__device__ float g_awv[(size_t)BSZ * CS * HD];      // tf32-rounded attention output

// tf32-rounded copies of GEMM sources
__device__ float r_input[(size_t)BSZ * CS * DIN];
__device__ float r_mem  [(size_t)BSZ * PS * DIN];
__device__ float r_pos  [(size_t)T * DIN];
__device__ float r_wkv  [(size_t)DIN * 2 * HD];
__device__ float r_wq   [(size_t)DIN * HD];
__device__ float r_wp   [(size_t)DIN * HD];
__device__ float r_wout [(size_t)HD * DIN];

// ---------------- tf32 helpers ----------------------------------------------
__device__ __forceinline__ uint32_t f2tf(float x) {
    uint32_t u;
    asm("cvt.rna.tf32.f32 %0, %1;" : "=r"(u) : "f"(x));
    return u;
}

#define MMA_TF32(c, a, b) \
    asm volatile("mma.sync.aligned.m16n8k8.row.col.f32.tf32.tf32.f32 " \
                 "{%0,%1,%2,%3},{%4,%5,%6,%7},{%8,%9},{%0,%1,%2,%3};" \
                 : "+f"(c[0]), "+f"(c[1]), "+f"(c[2]), "+f"(c[3]) \
                 : "r"(a[0]), "r"(a[1]), "r"(a[2]), "r"(a[3]), "r"(b[0]), "r"(b[1]))

__device__ __forceinline__ void cp16(uint32_t* smem_dst, const float* gmem_src) {
    uint32_t sa = (uint32_t)__cvta_generic_to_shared(smem_dst);
    asm volatile("cp.async.cg.shared.global [%0], [%1], 16;" :: "r"(sa), "l"(gmem_src));
}
#define CP_COMMIT asm volatile("cp.async.commit_group;")
#define CP_WAIT1  asm volatile("cp.async.wait_group 1;")
#define CP_WAIT0  asm volatile("cp.async.wait_group 0;")

// ---------------- prep: fused tf32 rounding of all sources + pa zero fixup ---
__device__ __forceinline__ void r4cp(float* dst, const float* src, int i) {
    float4 v = *(const float4*)(src + (size_t)i * 4);
    uint4 r;
    r.x = f2tf(v.x); r.y = f2tf(v.y); r.z = f2tf(v.z); r.w = f2tf(v.w);
    *(uint4*)(dst + (size_t)i * 4) = r;
}

__global__ void prep(const float* __restrict__ in_, const float* __restrict__ mem_,
                     const float* __restrict__ pos_, const float* __restrict__ wkv_,
                     const float* __restrict__ wq_, const float* __restrict__ wp_,
                     const float* __restrict__ wo_)
{
    int i = blockIdx.x * 256 + threadIdx.x;
    const int N1 = 1048576, N2 = 524288, N3 = 262144;
    if (i < N1) { r4cp(r_input, in_, i); return; }  i -= N1;
    if (i < N1) { r4cp(r_mem,   mem_, i); return; } i -= N1;
    if (i < N2) { r4cp(r_pos,   pos_, i); return; } i -= N2;
    if (i < N2) { r4cp(r_wkv,   wkv_, i); return; } i -= N2;
    if (i < N3) { r4cp(r_wq,    wq_, i); return; }  i -= N3;
    if (i < N3) { r4cp(r_wp,    wp_, i); return; }  i -= N3;
    if (i < N3) { r4cp(r_wout,  wo_, i); return; }  i -= N3;
    // pa zero-cell fixup: 16 heads x 4096 rows.
    // zero cells: sp=2049 -> j=M-2047 (valid only 2047<=M<=4094);
    //             sp=4098 -> j=M+2   (valid only M<=2045). Row 2046 & 4095: none.
    if (i < H * 4096) {
        int h = i >> 12, M = i & 4095;
        int j = -1;
        if (M >= 2047) { if (M <= 4094) j = M - 2047; }
        else if (M < 2046) j = M + 2;
        if (j >= 0) g_pa[((size_t)h * (BSZ * CS) + M) * T + j] = 0.f;
    }
}

// ---------------- GEMM (proven config: 128x128, 2-stage cp.async) ------------
#define AS_LD 36
#define BS_LD 136
#define STAGE_SZ (128 * AS_LD + 32 * BS_LD)
#define MM_SMEM (2 * STAGE_SZ * 4)

__device__ __forceinline__ void mma_chunk(float acc[4][4][4],
                                          const uint32_t* __restrict__ As,
                                          const uint32_t* __restrict__ Bs,
                                          int wm, int wn, int lane)
{
    int g = lane >> 2, t = lane & 3;
#pragma unroll
    for (int ks = 0; ks < 4; ks++) {
        uint32_t a[4][4];
#pragma unroll
        for (int mt = 0; mt < 4; mt++) {
            int row = wm * 64 + mt * 16 + g;
            int col = ks * 8 + t;
            a[mt][0] = As[row * AS_LD + col];
            a[mt][1] = As[(row + 8) * AS_LD + col];
            a[mt][2] = As[row * AS_LD + col + 4];
            a[mt][3] = As[(row + 8) * AS_LD + col + 4];
        }
        uint32_t b[4][2];
#pragma unroll
        for (int nt = 0; nt < 4; nt++) {
            int brow = ks * 8 + t;
            int bcol = wn * 32 + nt * 8 + g;
            b[nt][0] = Bs[brow * BS_LD + bcol];
            b[nt][1] = Bs[(brow + 4) * BS_LD + bcol];
        }
#pragma unroll
        for (int mt = 0; mt < 4; mt++)
#pragma unroll
            for (int nt = 0; nt < 4; nt++)
                MMA_TF32(acc[mt][nt], a[mt], b[nt]);
    }
}

template <bool RND>
__device__ __forceinline__ void store_C(float acc[4][4][4], float* C, int ldc,
                                        int m0, int n0, int wm, int wn, int lane)
{
    int g = lane >> 2, t = lane & 3;
#pragma unroll
    for (int mt = 0; mt < 4; mt++) {
#pragma unroll
        for (int nt = 0; nt < 4; nt++) {
            int row = m0 + wm * 64 + mt * 16 + g;
            int col = n0 + wn * 32 + nt * 8 + 2 * t;
            float v0 = acc[mt][nt][0], v1 = acc[mt][nt][1];
            float v2 = acc[mt][nt][2], v3 = acc[mt][nt][3];
            if (RND) {
                v0 = __uint_as_float(f2tf(v0)); v1 = __uint_as_float(f2tf(v1));
                v2 = __uint_as_float(f2tf(v2)); v3 = __uint_as_float(f2tf(v3));
            }
            *(float2*)(C + (size_t)row * ldc + col) = make_float2(v0, v1);
            *(float2*)(C + (size_t)(row + 8) * ldc + col) = make_float2(v2, v3);
        }
    }
}

__device__ __forceinline__ void stage_AB(uint32_t* As, uint32_t* Bs,
                                         const float* __restrict__ A, int lda,
                                         const float* __restrict__ B, int ldb,
                                         int m0, int n0, int k0, int tid)
{
#pragma unroll
    for (int i = 0; i < 4; i++) {
        int s = tid + i * 256;
        int row = s >> 3, kq = (s & 7) * 4;
        cp16(&As[row * AS_LD + kq], A + (size_t)(m0 + row) * lda + k0 + kq);
    }
#pragma unroll
    for (int i = 0; i < 4; i++) {
        int s = tid + i * 256;
        int k = s >> 5, n4 = (s & 31) * 4;
        cp16(&Bs[k * BS_LD + n4], B + (size_t)(k0 + k) * ldb + n0 + n4);
    }
}

__global__ __launch_bounds__(256, 2)
void mm_ca(const float* __restrict__ A, const float* __restrict__ B,
           float* __restrict__ C, int M, int N, int K)
{
    extern __shared__ uint32_t dsm[];
    int tid = threadIdx.x, lane = tid & 31, w = tid >> 5;
    int wm = w >> 2, wn = w & 3;
    int m0 = blockIdx.y * 128, n0 = blockIdx.x * 128;

    float acc[4][4][4];
#pragma unroll
    for (int i = 0; i < 4; i++)
#pragma unroll
        for (int j = 0; j < 4; j++)
#pragma unroll
            for (int r = 0; r < 4; r++) acc[i][j][r] = 0.f;

    uint32_t* As[2] = { dsm, dsm + STAGE_SZ };
    uint32_t* Bs[2] = { dsm + 128 * AS_LD, dsm + STAGE_SZ + 128 * AS_LD };

    stage_AB(As[0], Bs[0], A, K, B, N, m0, n0, 0, tid);  CP_COMMIT;
    stage_AB(As[1], Bs[1], A, K, B, N, m0, n0, 32, tid); CP_COMMIT;
    CP_WAIT1;
    __syncthreads();

    int NK = K >> 5;
    for (int k = 0; k < NK; k++) {
        int cur = k & 1;
        mma_chunk(acc, As[cur], Bs[cur], wm, wn, lane);
        __syncthreads();
        if (k + 2 < NK)
            stage_AB(As[cur], Bs[cur], A, K, B, N, m0, n0, (k + 2) * 32, tid);
        CP_COMMIT;
        CP_WAIT1;
        __syncthreads();
    }
    store_C<false>(acc, C, N, m0, n0, wm, wn, lane);
}

__device__ __forceinline__ void stage_A_kv(uint32_t* As, int m0, int k0, int tid)
{
#pragma unroll
    for (int i = 0; i < 4; i++) {
        int s = tid + i * 256;
        int row = s >> 3, kq = (s & 7) * 4;
        int grow = m0 + row;
        int b = grow >> 11, tl = grow & (T - 1);
        const float* Arow = (tl < PS) ? (r_mem + (size_t)(b * PS + tl) * DIN)
                                      : (r_input + (size_t)(b * CS + tl - PS) * DIN);
        cp16(&As[row * AS_LD + kq], Arow + k0 + kq);
    }
}
__device__ __forceinline__ void stage_B_kv(uint32_t* Bs, int n0, int k0, int tid)
{
#pragma unroll
    for (int i = 0; i < 4; i++) {
        int s = tid + i * 256;
        int k = s >> 5, n4 = (s & 31) * 4;
        cp16(&Bs[k * BS_LD + n4], r_wkv + (size_t)(k0 + k) * (2 * HD) + n0 + n4);
    }
}

__global__ __launch_bounds__(256, 2)
void mm_ca_kv()
{
    extern __shared__ uint32_t dsm[];
    int tid = threadIdx.x, lane = tid & 31, w = tid >> 5;
    int wm = w >> 2, wn = w & 3;
    int m0 = blockIdx.y * 128, n0 = blockIdx.x * 128;

    float acc[4][4][4];
#pragma unroll
    for (int i = 0; i < 4; i++)
#pragma unroll
        for (int j = 0; j < 4; j++)
#pragma unroll
            for (int r = 0; r < 4; r++) acc[i][j][r] = 0.f;

    uint32_t* As[2] = { dsm, dsm + STAGE_SZ };
    uint32_t* Bs[2] = { dsm + 128 * AS_LD, dsm + STAGE_SZ + 128 * AS_LD };

    stage_A_kv(As[0], m0, 0, tid);  stage_B_kv(Bs[0], n0, 0, tid);  CP_COMMIT;
    stage_A_kv(As[1], m0, 32, tid); stage_B_kv(Bs[1], n0, 32, tid); CP_COMMIT;
    CP_WAIT1;
    __syncthreads();

    const int NK = DIN >> 5;
    for (int k = 0; k < NK; k++) {
        int cur = k & 1;
        mma_chunk(acc, As[cur], Bs[cur], wm, wn, lane);
        __syncthreads();
        if (k + 2 < NK) {
            stage_A_kv(As[cur], m0, (k + 2) * 32, tid);
            stage_B_kv(Bs[cur], n0, (k + 2) * 32, tid);
        }
        CP_COMMIT;
        CP_WAIT1;
        __syncthreads();
    }
    // rounded store -> attn can cp.async K/V raw (bit-identical to f2tf at load)
    store_C<true>(acc, g_kv, 2 * HD, m0, n0, wm, wn, lane);
}

// ---------------- position-attn GEMM with SHIFT-ON-WRITE epilogue ------------
// computes pa[M'][j'] = (q[M']+v)·p[j'] and scatters to shifted dest (M, j), scaled.
#define PA_LD 68
#define PA_SMEM (2 * 128 * PA_LD * 4)   // 69632 B

__device__ __forceinline__ void scatter_pa(float* __restrict__ Ch, int rp, int cp, float val)
{
    int s = rp + cp;
    int a = (s <= 2046) ? 2 : ((s <= 4094) ? 1 : 0);
    int M = rp - a;
    if (M < 0) return;
    int j = s + 1 - 4096 + (a << 11);
    if (j > (M & (CS - 1)) + PS) return;     // masked cell — overwritten by -1e30 at read
    Ch[(size_t)M * T + j] = val * SCALEF;
}

__global__ __launch_bounds__(256, 2)
void mm_pa2(const float* __restrict__ vvec)
{
    extern __shared__ uint32_t psm[];
    uint32_t* As = psm;                  // 128 x 68 (q+v rows, K-major tf32)
    uint32_t* Bs = psm + 128 * PA_LD;    // 128 x 68 (p rows,   K-major tf32)

    int tid = threadIdx.x, lane = tid & 31, w = tid >> 5;
    int wm = w >> 2, wn = w & 3;
    int h = blockIdx.z;
    int m0 = blockIdx.y * 128, n0 = blockIdx.x * 128;
    int g = lane >> 2, t = lane & 3;

#pragma unroll
    for (int l = 0; l < 8; l++) {
        int idx = tid + l * 256;
        int r = idx >> 4, kq = (idx & 15) * 4;
        float4 a = *(const float4*)(g_q + (size_t)(m0 + r) * HD + h * D + kq);
        float4 vx = *(const float4*)(vvec + h * D + kq);
        uint4 ua;
        ua.x = f2tf(a.x + vx.x); ua.y = f2tf(a.y + vx.y);
        ua.z = f2tf(a.z + vx.z); ua.w = f2tf(a.w + vx.w);
        *(uint4*)&As[r * PA_LD + kq] = ua;
        float4 p4 = *(const float4*)(g_p + (size_t)(n0 + r) * HD + h * D + kq);
        uint4 ub;
        ub.x = f2tf(p4.x); ub.y = f2tf(p4.y); ub.z = f2tf(p4.z); ub.w = f2tf(p4.w);
        *(uint4*)&Bs[r * PA_LD + kq] = ub;
    }
    __syncthreads();

    float acc[4][4][4];
#pragma unroll
    for (int i = 0; i < 4; i++)
#pragma unroll
        for (int j = 0; j < 4; j++)
#pragma unroll
            for (int r = 0; r < 4; r++) acc[i][j][r] = 0.f;

#pragma unroll
    for (int ks = 0; ks < 8; ks++) {
        uint32_t a[4][4];
#pragma unroll
        for (int mt = 0; mt < 4; mt++) {
            int row = wm * 64 + mt * 16 + g;
            int col = ks * 8 + t;
            a[mt][0] = As[row * PA_LD + col];
            a[mt][1] = As[(row + 8) * PA_LD + col];
            a[mt][2] = As[row * PA_LD + col + 4];
            a[mt][3] = As[(row + 8) * PA_LD + col + 4];
        }
        uint32_t b[4][2];
#pragma unroll
        for (int nt = 0; nt < 4; nt++) {
            int bcol = wn * 32 + nt * 8 + g;
            b[nt][0] = Bs[bcol * PA_LD + ks * 8 + t];
            b[nt][1] = Bs[bcol * PA_LD + ks * 8 + t + 4];
        }
#pragma unroll
        for (int mt = 0; mt < 4; mt++)
#pragma unroll
            for (int nt = 0; nt < 4; nt++)
                MMA_TF32(acc[mt][nt], a[mt], b[nt]);
    }

    float* Ch = g_pa + (size_t)h * (BSZ * CS) * T;
#pragma unroll
    for (int mt = 0; mt < 4; mt++) {
#pragma unroll
        for (int nt = 0; nt < 4; nt++) {
            int row0 = m0 + wm * 64 + mt * 16 + g;
            int col0 = n0 + wn * 32 + nt * 8 + 2 * t;
            scatter_pa(Ch, row0,     col0,     acc[mt][nt][0]);
            scatter_pa(Ch, row0,     col0 + 1, acc[mt][nt][1]);
            scatter_pa(Ch, row0 + 8, col0,     acc[mt][nt][2]);
            scatter_pa(Ch, row0 + 8, col0 + 1, acc[mt][nt][3]);
        }
    }
}

// ---------------- flash attention: cp.async K/V + contiguous pos reads --------
#define AT_LD 68
#define ATT_SMEM ((2 * 2 * 64 * AT_LD + 128 * AT_LD) * 4)   // 104448 B

__device__ __forceinline__ void stage_kv_tile(uint32_t* buf, int b, int h, int j0, int tid)
{
#pragma unroll
    for (int l = 0; l < 4; l++) {
        int idx = tid + l * 256;
        int r = idx >> 4, q = idx & 15;
        const float* src = g_kv + (size_t)(b * T + j0 + r) * (2 * HD) + h * D + q * 4;
        cp16(buf + r * AT_LD + q * 4, src);                   // K
        cp16(buf + 64 * AT_LD + r * AT_LD + q * 4, src + HD); // V
    }
}

__global__ __launch_bounds__(256, 2)
void attn_tc(const float* __restrict__ u)
{
    extern __shared__ uint32_t sm[];
    uint32_t* Ps = sm + 2 * 2 * 64 * AT_LD;   // 128 x 68 (Q staging, then P)

    int tid = threadIdx.x, lane = tid & 31, w = tid >> 5;
    int b = blockIdx.z, h = blockIdx.y;
    int q0 = (int)(gridDim.x - 1 - blockIdx.x) * 128;
    int g = lane >> 2, t = lane & 3;

    // Q(+u), pre-scaled by SCALEF (exact power of 2), tf32
    for (int i = tid; i < 128 * 16; i += 256) {
        int r = i >> 4, d4 = (i & 15) * 4;
        float4 qv = *(const float4*)(g_q + (size_t)(b * CS + q0 + r) * HD + h * D + d4);
        float4 uv = *(const float4*)(u + h * D + d4);
        Ps[r * AT_LD + d4 + 0] = f2tf((qv.x + uv.x) * SCALEF);
        Ps[r * AT_LD + d4 + 1] = f2tf((qv.y + uv.y) * SCALEF);
        Ps[r * AT_LD + d4 + 2] = f2tf((qv.z + uv.z) * SCALEF);
        Ps[r * AT_LD + d4 + 3] = f2tf((qv.w + uv.w) * SCALEF);
    }
    __syncthreads();

    uint32_t qf[8][4];
    {
        int r0 = w * 16 + g;
#pragma unroll
        for (int ks = 0; ks < 8; ks++) {
            qf[ks][0] = Ps[r0 * AT_LD + ks * 8 + t];
            qf[ks][1] = Ps[(r0 + 8) * AT_LD + ks * 8 + t];
            qf[ks][2] = Ps[r0 * AT_LD + ks * 8 + t + 4];
            qf[ks][3] = Ps[(r0 + 8) * AT_LD + ks * 8 + t + 4];
        }
    }

    float of[8][4];
#pragma unroll
    for (int nt = 0; nt < 8; nt++)
#pragma unroll
        for (int r = 0; r < 4; r++) of[nt][r] = 0.f;
    float m0r = -1e30f, m1r = -1e30f, l0 = 0.f, l1 = 0.f;

    int iq_g = q0 + w * 16 + g;
    int Mrow_g = b * CS + iq_g;
    int pr0 = (w * 16 + g) * AT_LD, pr8 = (w * 16 + g + 8) * AT_LD;
    int ntiles = q0 / 64 + 18;

    const float* pab0 = g_pa + ((size_t)h * (BSZ * CS) + Mrow_g) * T;
    const float* pab8 = pab0 + (size_t)8 * T;

    stage_kv_tile(sm, b, h, 0, tid);   // tile 0 -> buf 0
    CP_COMMIT;

    for (int tt = 0; tt < ntiles; tt++) {
        int cur = tt & 1;
        uint32_t* Kc = sm + cur * (2 * 64 * AT_LD);
        uint32_t* Vc = Kc + 64 * AT_LD;
        int j0 = tt * 64;

        __syncthreads();   // all warps done reading buf[1-cur] (iter tt-1)
        if (tt + 1 < ntiles) {
            stage_kv_tile(sm + (1 - cur) * (2 * 64 * AT_LD), b, h, j0 + 64, tid);
            CP_COMMIT;
            CP_WAIT1;      // tile tt arrived (tt+1 in flight)
        } else {
            CP_WAIT0;
        }
        __syncthreads();

        // S = (Q+u)*SCALE @ K^T
        float sf[8][4];
#pragma unroll
        for (int nt = 0; nt < 8; nt++) {
            sf[nt][0] = sf[nt][1] = sf[nt][2] = sf[nt][3] = 0.f;
#pragma unroll
            for (int ks = 0; ks < 8; ks++) {
                uint32_t bb[2];
                bb[0] = Kc[(nt * 8 + g) * AT_LD + ks * 8 + t];
                bb[1] = Kc[(nt * 8 + g) * AT_LD + ks * 8 + t + 4];
                MMA_TF32(sf[nt], qf[ks], bb);
            }
        }

        // add pre-shifted pre-scaled pos (contiguous float2 loads) + mask
        bool need_mask = (tt >= ntiles - 2);
#pragma unroll
        for (int nt = 0; nt < 8; nt++) {
            int j = j0 + nt * 8 + 2 * t;
            float2 p0 = __ldg((const float2*)(pab0 + j));
            float2 p8 = __ldg((const float2*)(pab8 + j));
            sf[nt][0] += p0.x; sf[nt][1] += p0.y;
            sf[nt][2] += p8.x; sf[nt][3] += p8.y;
            if (need_mask) {
                int lim0 = iq_g + PS, lim1 = lim0 + 8;
                if (j     > lim0) sf[nt][0] = -1e30f;
                if (j + 1 > lim0) sf[nt][1] = -1e30f;
                if (j     > lim1) sf[nt][2] = -1e30f;
                if (j + 1 > lim1) sf[nt][3] = -1e30f;
            }
        }

        // online softmax
        float tm0 = -1e30f, tm1 = -1e30f;
#pragma unroll
        for (int nt = 0; nt < 8; nt++) {
            tm0 = fmaxf(tm0, fmaxf(sf[nt][0], sf[nt][1]));
            tm1 = fmaxf(tm1, fmaxf(sf[nt][2], sf[nt][3]));
        }
        tm0 = fmaxf(tm0, __shfl_xor_sync(0xffffffffu, tm0, 1));
        tm0 = fmaxf(tm0, __shfl_xor_sync(0xffffffffu, tm0, 2));
        tm1 = fmaxf(tm1, __shfl_xor_sync(0xffffffffu, tm1, 1));
        tm1 = fmaxf(tm1, __shfl_xor_sync(0xffffffffu, tm1, 2));
        float nm0 = fmaxf(m0r, tm0), nm1 = fmaxf(m1r, tm1);
        float cr0 = __expf(m0r - nm0), cr1 = __expf(m1r - nm1);

        float ps0 = 0.f, ps1 = 0.f;
#pragma unroll
        for (int nt = 0; nt < 8; nt++) {
            float e0 = __expf(sf[nt][0] - nm0);
            float e1 = __expf(sf[nt][1] - nm0);
            float e2 = __expf(sf[nt][2] - nm1);
            float e3 = __expf(sf[nt][3] - nm1);
            int col = nt * 8 + 2 * t;
            Ps[pr0 + col]     = f2tf(e0);
            Ps[pr0 + col + 1] = f2tf(e1);
            Ps[pr8 + col]     = f2tf(e2);
            Ps[pr8 + col + 1] = f2tf(e3);
            ps0 += e0 + e1;
            ps1 += e2 + e3;
        }
        ps0 += __shfl_xor_sync(0xffffffffu, ps0, 1);
        ps0 += __shfl_xor_sync(0xffffffffu, ps0, 2);
        ps1 += __shfl_xor_sync(0xffffffffu, ps1, 1);
        ps1 += __shfl_xor_sync(0xffffffffu, ps1, 2);
        l0 = l0 * cr0 + ps0;
        l1 = l1 * cr1 + ps1;
        m0r = nm0; m1r = nm1;
#pragma unroll
        for (int nt = 0; nt < 8; nt++) {
            of[nt][0] *= cr0; of[nt][1] *= cr0;
            of[nt][2] *= cr1; of[nt][3] *= cr1;
        }
        __syncwarp();

        uint32_t af[8][4];
#pragma unroll
        for (int ks = 0; ks < 8; ks++) {
            af[ks][0] = Ps[pr0 + ks * 8 + t];
            af[ks][1] = Ps[pr8 + ks * 8 + t];
            af[ks][2] = Ps[pr0 + ks * 8 + t + 4];
            af[ks][3] = Ps[pr8 + ks * 8 + t + 4];
        }
#pragma unroll
        for (int nt = 0; nt < 8; nt++) {
#pragma unroll
            for (int ks = 0; ks < 8; ks++) {
                uint32_t bb[2];
                bb[0] = Vc[(ks * 8 + t) * AT_LD + nt * 8 + g];
                bb[1] = Vc[(ks * 8 + t + 4) * AT_LD + nt * 8 + g];
                MMA_TF32(of[nt], af[ks], bb);
            }
        }
        __syncwarp();
    }

    float i0 = 1.f / l0, i1 = 1.f / l1;
    int orow = b * CS + q0 + w * 16 + g;
#pragma unroll
    for (int nt = 0; nt < 8; nt++) {
        int col = h * D + nt * 8 + 2 * t;
        float2 v0 = make_float2(__uint_as_float(f2tf(of[nt][0] * i0)),
                                __uint_as_float(f2tf(of[nt][1] * i0)));
        float2 v1 = make_float2(__uint_as_float(f2tf(of[nt][2] * i1)),
                                __uint_as_float(f2tf(of[nt][3] * i1)));
        *(float2*)(g_awv + (size_t)orow * HD + col) = v0;
        *(float2*)(g_awv + (size_t)(orow + 8) * HD + col) = v1;
    }
}

// ---------------- launch -------------------------------------------------------
extern "C" void kernel_launch(void* const* d_in, const int* in_sizes, int n_in,
                              void* d_out, int out_size)
{
    const float* input  = (const float*)d_in[0];
    const float* pos    = (const float*)d_in[1];
    const float* memory = (const float*)d_in[2];
    const float* u      = (const float*)d_in[3];
    const float* v      = (const float*)d_in[4];
    const float* Wkv    = (const float*)d_in[5];
    const float* Wq     = (const float*)d_in[6];
    const float* Wp     = (const float*)d_in[7];
    const float* Wout   = (const float*)d_in[8];
    float* out = (float*)d_out;

    float *pq, *pp, *pawv;
    float *pri, *prp, *prq, *prwp, *prwo;
    cudaGetSymbolAddress((void**)&pq,   g_q);
    cudaGetSymbolAddress((void**)&pp,   g_p);
    cudaGetSymbolAddress((void**)&pawv, g_awv);
    cudaGetSymbolAddress((void**)&pri,  r_input);
    cudaGetSymbolAddress((void**)&prp,  r_pos);
    cudaGetSymbolAddress((void**)&prq,  r_wq);
    cudaGetSymbolAddress((void**)&prwp, r_wp);
    cudaGetSymbolAddress((void**)&prwo, r_wout);

    cudaFuncSetAttribute(mm_ca,    cudaFuncAttributeMaxDynamicSharedMemorySize, MM_SMEM);
    cudaFuncSetAttribute(mm_ca_kv, cudaFuncAttributeMaxDynamicSharedMemorySize, MM_SMEM);
    cudaFuncSetAttribute(mm_pa2,   cudaFuncAttributeMaxDynamicSharedMemorySize, PA_SMEM);
    cudaFuncSetAttribute(attn_tc,  cudaFuncAttributeMaxDynamicSharedMemorySize, ATT_SMEM);

    // launch 0: fused tf32 pre-round of all sources + pa zero-cell fixup
    prep<<<15616, 256>>>(input, memory, pos, Wkv, Wq, Wp, Wout);
    // launch 1: kv = [memory; input] @ W_kv   (8192 x 2048 x 1024), rounded store
    mm_ca_kv<<<dim3(16, 64), 256, MM_SMEM>>>();
    // launch 2: q = input @ W_q               (4096 x 1024 x 1024)
    mm_ca<<<dim3(8, 32), 256, MM_SMEM>>>(pri, prq, pq, BSZ * CS, HD, DIN);
    // launch 3: p = pos_embs @ W_p            (2048 x 1024 x 1024)
    mm_ca<<<dim3(8, 16), 256, MM_SMEM>>>(prp, prwp, pp, T, HD, DIN);
    // launch 4: pos-attn per head, shift-on-write  (16 x 4096 x 2048 x 64)
    mm_pa2<<<dim3(16, 32, H), 256, PA_SMEM>>>(v);
    // launch 5 (ncu-captured): flash attention
    attn_tc<<<dim3(8, H, BSZ), 256, ATT_SMEM>>>(u);
    // launch 6: out = awv @ W_out             (4096 x 1024 x 1024)
    mm_ca<<<dim3(8, 32), 256, MM_SMEM>>>(pawv, prwo, out, BSZ * CS, DIN, HD);
}